// round 11
// baseline (speedup 1.0000x reference)
#include <cuda_runtime.h>
#include <cuda_bf16.h>
#include <cstdint>
#include <math.h>

// Problem sizes (fixed)
#define BB 16384
#define DD 512

// ---------------- scratch (device globals; no allocs allowed) ----------------
__device__ __nv_bfloat16 g_Vb[512 * 512];    // B1: V bf16, rows n=(e,r), k=d contiguous
__device__ __nv_bfloat16 g_Utb[512 * 512];   // B2: Ut[n=d][k=e*64+r] bf16 (C folded into U)
__device__ __nv_bfloat16 g_Xb[BB * 512];     // x bf16 (A operand GEMM1)
__device__ __nv_bfloat16 g_Hb[BB * 512];     // h = g*xv bf16 (A operand GEMM2)
__device__ float g_gate[BB * 8];             // softmax gates

// ---------------- helpers ----------------
__device__ __forceinline__ uint32_t smem_u32(const void* p) {
    uint32_t a;
    asm("{ .reg .u64 t; cvta.to.shared.u64 t, %1; cvt.u32.u64 %0, t; }" : "=r"(a) : "l"(p));
    return a;
}
__device__ __forceinline__ void cp16s(uint32_t s, const void* g) {
    asm volatile("cp.async.cg.shared.global [%0], [%1], 16;" :: "r"(s), "l"(g));
}
__device__ __forceinline__ void ldsm4(uint32_t* r, uint32_t addr) {
    asm volatile("ldmatrix.sync.aligned.m8n8.x4.shared.b16 {%0,%1,%2,%3}, [%4];"
        : "=r"(r[0]), "=r"(r[1]), "=r"(r[2]), "=r"(r[3]) : "r"(addr));
}
// m16n8k16 bf16 MMA, fp32 accum
__device__ __forceinline__ void mma_bf16(float* d, const uint32_t* a, uint32_t b0, uint32_t b1) {
    asm volatile(
        "mma.sync.aligned.m16n8k16.row.col.f32.bf16.bf16.f32 "
        "{%0,%1,%2,%3}, {%4,%5,%6,%7}, {%8,%9}, {%0,%1,%2,%3};"
        : "+f"(d[0]), "+f"(d[1]), "+f"(d[2]), "+f"(d[3])
        : "r"(a[0]), "r"(a[1]), "r"(a[2]), "r"(a[3]), "r"(b0), "r"(b1));
}

// smem geometry: chunk = 128 rows x 64 bf16 (128B) per operand, padded to 144B/row.
static constexpr int ROWB = 144;                 // bytes per smem row
static constexpr int STAGE_B = 128 * ROWB;       // 18432 B per operand per stage
static constexpr int OPS_B = 2 * STAGE_B;        // 36864 B per stage (A + B)
static constexpr int NSTAGE = 3;
static constexpr int SM_TOTAL = NSTAGE * OPS_B;  // 110592 B

// ---------------- fused prep: V->bf16 (blocks 0..255)  +  fold C into U (blocks 256..319) ----
__global__ void prep_kernel(const float* __restrict__ V,
                            const float* __restrict__ U, const float* __restrict__ C) {
    __shared__ float Cs[64][64];
    __shared__ float Us[64][65];
    int t = threadIdx.x;

    if (blockIdx.x < 256) {
        // V fp32 -> bf16, 4 floats per thread
        int i = blockIdx.x * 256 + t;             // 0..65535 (x4 floats)
        float4 v = reinterpret_cast<const float4*>(V)[i];
        __nv_bfloat162 lo = __floats2bfloat162_rn(v.x, v.y);
        __nv_bfloat162 hi = __floats2bfloat162_rn(v.z, v.w);
        uint2 o;
        o.x = *reinterpret_cast<uint32_t*>(&lo);
        o.y = *reinterpret_cast<uint32_t*>(&hi);
        reinterpret_cast<uint2*>(g_Vb)[i] = o;
        return;
    }

    int bid = blockIdx.x - 256;                   // 0..63
    int e = bid >> 3;                             // 0..7
    int d0 = (bid & 7) * 64;                      // 0..511 step 64

    for (int i = t; i < 4096; i += 256) Cs[i >> 6][i & 63] = C[e * 4096 + i];
    for (int i = t; i < 4096; i += 256) Us[i >> 6][i & 63] = U[e * 32768 + d0 * 64 + i];
    __syncthreads();

    for (int o = t; o < 4096; o += 256) {
        int r = o >> 6, dl = o & 63;
        float s = 0.f;
#pragma unroll
        for (int ss = 0; ss < 64; ss++) s += Us[dl][ss] * Cs[r][ss];
        g_Utb[(size_t)(d0 + dl) * 512 + e * 64 + r] = __float2bfloat16(s);
    }
}

// ---------------- gate + x->bf16 fused: g = softmax(x@Wg^T + bg); g_Xb = bf16(x) ----------------
__global__ void gate_cvt_kernel(const float* __restrict__ x, const float* __restrict__ Wg,
                                const float* __restrict__ bg) {
    int warp = blockIdx.x * (blockDim.x >> 5) + (threadIdx.x >> 5);
    int lane = threadIdx.x & 31;
    if (warp >= BB) return;
    int m = warp;

    const float4* xr = reinterpret_cast<const float4*>(x + (size_t)m * 512);
    uint2* xb = reinterpret_cast<uint2*>(g_Xb + (size_t)m * 512);

    // hoist all x loads (MLP=4 on the DRAM-latency path)
    float4 xv[4];
#pragma unroll
    for (int i = 0; i < 4; i++) xv[i] = xr[lane + i * 32];
#pragma unroll
    for (int i = 0; i < 4; i++) {
        __nv_bfloat162 lo = __floats2bfloat162_rn(xv[i].x, xv[i].y);
        __nv_bfloat162 hi = __floats2bfloat162_rn(xv[i].z, xv[i].w);
        uint2 o;
        o.x = *reinterpret_cast<uint32_t*>(&lo);
        o.y = *reinterpret_cast<uint32_t*>(&hi);
        xb[lane + i * 32] = o;
    }

    float acc[8] = {0.f, 0.f, 0.f, 0.f, 0.f, 0.f, 0.f, 0.f};
#pragma unroll
    for (int i = 0; i < 4; i++) {
#pragma unroll
        for (int e = 0; e < 8; e++) {
            float4 wv = reinterpret_cast<const float4*>(Wg + e * 512)[lane + i * 32];
            acc[e] += xv[i].x * wv.x + xv[i].y * wv.y + xv[i].z * wv.z + xv[i].w * wv.w;
        }
    }
#pragma unroll
    for (int off = 16; off; off >>= 1)
#pragma unroll
        for (int e = 0; e < 8; e++) acc[e] += __shfl_xor_sync(0xFFFFFFFFu, acc[e], off);

    if (lane == 0) {
        float logit[8], mx = -1e30f;
#pragma unroll
        for (int e = 0; e < 8; e++) { logit[e] = acc[e] + bg[e]; mx = fmaxf(mx, logit[e]); }
        float ex[8], s = 0.f;
#pragma unroll
        for (int e = 0; e < 8; e++) { ex[e] = expf(logit[e] - mx); s += ex[e]; }
        float inv = 1.f / s;
#pragma unroll
        for (int e = 0; e < 8; e++) g_gate[m * 8 + e] = ex[e] * inv;
    }
}

// ---------------- bf16 mma.sync GEMM ----------------
// D[128,128] tile; 128 thr, 4 warps in 2(m) x 2(n), warp tile 64x64.
// K chunks of 64, 3-stage cp.async pipeline, ONE __syncthreads per chunk, 2 CTAs/SM.
// mode 1: A=g_Xb, B=g_Vb; epilogue h = g*xv -> g_Hb (bf16)
// mode 2: A=g_Hb, B=g_Utb; epilogue out = x0*gproj + g@b + x*sum(g)
__global__ __launch_bounds__(128, 2) void gemm_mma(const __nv_bfloat16* __restrict__ A,
                                                   const __nv_bfloat16* __restrict__ Bp,
                                                   int mode,
                                                   const float* __restrict__ x0,
                                                   const float* __restrict__ x,
                                                   const float* __restrict__ bbias,
                                                   float* __restrict__ out) {
    extern __shared__ __align__(16) float smemf[];
    const uint32_t sb = smem_u32(smemf);
    const int tid = threadIdx.x;
    const int wid = tid >> 5, lane = tid & 31;
    const int g = lane >> 2, tg = lane & 3;       // accum frag coords
    const int wm = wid & 1, wn = wid >> 1;        // warp m (0..1), n (0..1)
    const int n0 = blockIdx.x * 128, m0 = blockIdx.y * 128;

    float acc[4][8][4];
#pragma unroll
    for (int mi = 0; mi < 4; mi++)
#pragma unroll
        for (int ni = 0; ni < 8; ni++)
#pragma unroll
            for (int q = 0; q < 4; q++) acc[mi][ni][q] = 0.f;

    // ldmatrix lane->address maps (add stage*OPS_B + ks*32 at use)
    const int arow_l = (lane & 7) + ((lane >> 3) & 1) * 8;
    const int ahalf  = ((lane >> 4) & 1) * 16;
    uint32_t a_addr[4];
#pragma unroll
    for (int mi = 0; mi < 4; mi++)
        a_addr[mi] = sb + (uint32_t)(wm * 64 + mi * 16 + arow_l) * ROWB + ahalf;
    const int brow_l = (lane & 7) + ((lane >> 4) & 1) * 8;
    const int bhalf  = ((lane >> 3) & 1) * 16;
    uint32_t b_addr[4];
#pragma unroll
    for (int bj = 0; bj < 4; bj++)
        b_addr[bj] = sb + STAGE_B + (uint32_t)(wn * 64 + bj * 16 + brow_l) * ROWB + bhalf;

    // chunk load: 128 rows x 128B per operand; 16 cp16 per thread
#define LOADCHUNK(SLOT, KC) do {                                                         \
        const __nv_bfloat16* _ag = A  + (size_t)m0 * 512 + (KC) * 64;                    \
        const __nv_bfloat16* _bg = Bp + (size_t)n0 * 512 + (KC) * 64;                    \
        uint32_t _ab = sb + (SLOT) * OPS_B;                                              \
        uint32_t _bb = _ab + STAGE_B;                                                    \
        _Pragma("unroll")                                                                \
        for (int j = 0; j < 8; j++) {                                                    \
            int id = tid + j * 128;                                                      \
            int row = id >> 3, seg = id & 7;                                             \
            cp16s(_ab + row * ROWB + seg * 16, _ag + (size_t)row * 512 + seg * 8);       \
            cp16s(_bb + row * ROWB + seg * 16, _bg + (size_t)row * 512 + seg * 8);       \
        }                                                                                \
        asm volatile("cp.async.commit_group;");                                          \
    } while (0)

    LOADCHUNK(0, 0);
    LOADCHUNK(1, 1);

    for (int c = 0; c < 8; c++) {
        if (c < 7) asm volatile("cp.async.wait_group 1;");   // chunk c arrived
        else       asm volatile("cp.async.wait_group 0;");
        __syncthreads();                                     // also: all warps done with c-1
        if (c + 2 < 8) LOADCHUNK((c + 2) % 3, c + 2);        // overwrites slot of chunk c-1

        const uint32_t soff = (uint32_t)(c % 3) * OPS_B;
#pragma unroll
        for (int ks = 0; ks < 4; ks++) {
            const uint32_t ko = soff + ks * 32;
            uint32_t a[4][4];
#pragma unroll
            for (int mi = 0; mi < 4; mi++) ldsm4(a[mi], a_addr[mi] + ko);
            uint32_t b[4][4];
#pragma unroll
            for (int bj = 0; bj < 4; bj++) ldsm4(b[bj], b_addr[bj] + ko);
#pragma unroll
            for (int ni = 0; ni < 8; ni++) {
                uint32_t b0 = b[ni >> 1][(ni & 1) * 2];
                uint32_t b1 = b[ni >> 1][(ni & 1) * 2 + 1];
#pragma unroll
                for (int mi = 0; mi < 4; mi++) mma_bf16(acc[mi][ni], a[mi], b0, b1);
            }
        }
    }
#undef LOADCHUNK

    // ---------------- epilogue ----------------
    // acc[mi][ni]: rows r0 = m0+wm*64+mi*16+g (c0,c1), r1 = r0+8 (c2,c3);
    // cols = n0 + wn*64 + ni*8 + 2*tg (+1)
    if (mode == 1) {
        const int e_w = (n0 + wn * 64) >> 6;   // expert constant per warp column strip
#pragma unroll
        for (int mi = 0; mi < 4; mi++) {
            int r0 = m0 + wm * 64 + mi * 16 + g, r1 = r0 + 8;
            float g0 = g_gate[r0 * 8 + e_w];
            float g1 = g_gate[r1 * 8 + e_w];
#pragma unroll
            for (int ni = 0; ni < 8; ni++) {
                int cc = n0 + wn * 64 + ni * 8 + 2 * tg;
                __nv_bfloat162 h0 = __floats2bfloat162_rn(g0 * acc[mi][ni][0], g0 * acc[mi][ni][1]);
                __nv_bfloat162 h1 = __floats2bfloat162_rn(g1 * acc[mi][ni][2], g1 * acc[mi][ni][3]);
                *reinterpret_cast<__nv_bfloat162*>(&g_Hb[(size_t)r0 * 512 + cc]) = h0;
                *reinterpret_cast<__nv_bfloat162*>(&g_Hb[(size_t)r1 * 512 + cc]) = h1;
            }
        }
    } else {
        // stage b columns for this CTA: bs[e][0..127]
        __syncthreads();
        float* bs = smemf;
        for (int i = tid; i < 8 * 128; i += 128)
            bs[i] = bbias[(i >> 7) * 512 + n0 + (i & 127)];
        __syncthreads();

#pragma unroll
        for (int ni = 0; ni < 8; ni++) {
            int cl = wn * 64 + ni * 8 + 2 * tg;
            int cc = n0 + cl;
            float bc0[8], bc1[8];
#pragma unroll
            for (int e = 0; e < 8; e++) { bc0[e] = bs[e * 128 + cl]; bc1[e] = bs[e * 128 + cl + 1]; }
#pragma unroll
            for (int mi = 0; mi < 4; mi++) {
                int r0 = m0 + wm * 64 + mi * 16 + g;
#pragma unroll
                for (int rr = 0; rr < 2; rr++) {
                    int r = r0 + rr * 8;
                    float4 ga = *reinterpret_cast<const float4*>(g_gate + r * 8);
                    float4 gb = *reinterpret_cast<const float4*>(g_gate + r * 8 + 4);
                    float gs = ga.x + ga.y + ga.z + ga.w + gb.x + gb.y + gb.z + gb.w;
                    float q0 = ga.x * bc0[0] + ga.y * bc0[1] + ga.z * bc0[2] + ga.w * bc0[3]
                             + gb.x * bc0[4] + gb.y * bc0[5] + gb.z * bc0[6] + gb.w * bc0[7];
                    float q1 = ga.x * bc1[0] + ga.y * bc1[1] + ga.z * bc1[2] + ga.w * bc1[3]
                             + gb.x * bc1[4] + gb.y * bc1[5] + gb.z * bc1[6] + gb.w * bc1[7];
                    size_t off = (size_t)r * 512 + cc;
                    float2 xv0 = *reinterpret_cast<const float2*>(x0 + off);
                    float2 xv  = *reinterpret_cast<const float2*>(x + off);
                    float a0 = acc[mi][ni][rr ? 2 : 0];
                    float a1 = acc[mi][ni][rr ? 3 : 1];
                    float2 o;
                    o.x = fmaf(xv0.x, a0, fmaf(xv.x, gs, q0));
                    o.y = fmaf(xv0.y, a1, fmaf(xv.y, gs, q1));
                    *reinterpret_cast<float2*>(out + off) = o;
                }
            }
        }
    }
}

// ---------------- launch ----------------
extern "C" void kernel_launch(void* const* d_in, const int* in_sizes, int n_in,
                              void* d_out, int out_size) {
    const float* x0 = (const float*)d_in[0];   // [B, D]
    const float* x  = (const float*)d_in[1];   // [B, D]
    const float* U  = (const float*)d_in[2];   // [E, D, R]
    const float* V  = (const float*)d_in[3];   // [E, R, D]
    const float* C  = (const float*)d_in[4];   // [E, R, R]
    const float* b  = (const float*)d_in[5];   // [E, D]
    const float* Wg = (const float*)d_in[6];   // [E, D]
    const float* bg = (const float*)d_in[7];   // [E]
    float* out = (float*)d_out;

    cudaFuncSetAttribute(gemm_mma, cudaFuncAttributeMaxDynamicSharedMemorySize, SM_TOTAL);

    prep_kernel<<<320, 256>>>(V, U, C);          // V->bf16 + C-fold
    gate_cvt_kernel<<<2048, 256>>>(x, Wg, bg);   // gates + x->bf16 in one pass

    const __nv_bfloat16 *Xb, *Vb, *Hb, *Utb;
    cudaGetSymbolAddress((void**)&Xb, g_Xb);
    cudaGetSymbolAddress((void**)&Vb, g_Vb);
    cudaGetSymbolAddress((void**)&Hb, g_Hb);
    cudaGetSymbolAddress((void**)&Utb, g_Utb);

    // GEMM1: g_Hb = g * (x @ Vflat^T)
    gemm_mma<<<dim3(4, 128), 128, SM_TOTAL>>>(Xb, Vb, 1, nullptr, nullptr, nullptr, nullptr);
    // GEMM2: out = x0 * (g_Hb @ Ut^T) + g@b + x*sum(g)
    gemm_mma<<<dim3(4, 128), 128, SM_TOTAL>>>(Hb, Utb, 2, x0, x, b, out);
}

// round 12
// speedup vs baseline: 1.1337x; 1.1337x over previous
#include <cuda_runtime.h>
#include <cuda_bf16.h>
#include <cstdint>
#include <math.h>

// Problem sizes (fixed)
#define BB 16384
#define DD 512

// ---------------- scratch (device globals; no allocs allowed) ----------------
__device__ __nv_bfloat16 g_Vb[512 * 512];    // B1: V bf16, rows n=(e,r), k=d contiguous
__device__ __nv_bfloat16 g_Utb[512 * 512];   // B2: Ut[n=d][k=e*64+r] bf16 (C folded into U)
__device__ __nv_bfloat16 g_Xb[BB * 512];     // x bf16 (A operand GEMM1)
__device__ __nv_bfloat16 g_Hb[BB * 512];     // h = g*xv bf16 (A operand GEMM2)
__device__ float g_gate[BB * 8];             // softmax gates

// ---------------- helpers ----------------
__device__ __forceinline__ uint32_t smem_u32(const void* p) {
    uint32_t a;
    asm("{ .reg .u64 t; cvta.to.shared.u64 t, %1; cvt.u32.u64 %0, t; }" : "=r"(a) : "l"(p));
    return a;
}
__device__ __forceinline__ void cp16s(uint32_t s, const void* g) {
    asm volatile("cp.async.cg.shared.global [%0], [%1], 16;" :: "r"(s), "l"(g));
}
__device__ __forceinline__ void ldsm4(uint32_t* r, uint32_t addr) {
    asm volatile("ldmatrix.sync.aligned.m8n8.x4.shared.b16 {%0,%1,%2,%3}, [%4];"
        : "=r"(r[0]), "=r"(r[1]), "=r"(r[2]), "=r"(r[3]) : "r"(addr));
}
// m16n8k16 bf16 MMA, fp32 accum
__device__ __forceinline__ void mma_bf16(float* d, const uint32_t* a, uint32_t b0, uint32_t b1) {
    asm volatile(
        "mma.sync.aligned.m16n8k16.row.col.f32.bf16.bf16.f32 "
        "{%0,%1,%2,%3}, {%4,%5,%6,%7}, {%8,%9}, {%0,%1,%2,%3};"
        : "+f"(d[0]), "+f"(d[1]), "+f"(d[2]), "+f"(d[3])
        : "r"(a[0]), "r"(a[1]), "r"(a[2]), "r"(a[3]), "r"(b0), "r"(b1));
}

// smem geometry: chunk = 128 rows x 64 bf16 (128B) per operand, padded to 144B/row.
static constexpr int ROWB = 144;                 // bytes per smem row
static constexpr int STAGE_B = 128 * ROWB;       // 18432 B per operand per stage
static constexpr int OPS_B = 2 * STAGE_B;        // 36864 B per stage (A + B)
static constexpr int SM_TOTAL = 2 * OPS_B;       // 73728 B (2 stages) — R10 proven config

// ---------------- fused prep: V->bf16 (blocks 0..255)  +  fold C into U (blocks 256..319) ----
__global__ void prep_kernel(const float* __restrict__ V,
                            const float* __restrict__ U, const float* __restrict__ C) {
    __shared__ float Cs[64][64];
    __shared__ float Us[64][65];
    int t = threadIdx.x;

    if (blockIdx.x < 256) {
        // V fp32 -> bf16, 4 floats per thread
        int i = blockIdx.x * 256 + t;             // 0..65535 (x4 floats)
        float4 v = reinterpret_cast<const float4*>(V)[i];
        __nv_bfloat162 lo = __floats2bfloat162_rn(v.x, v.y);
        __nv_bfloat162 hi = __floats2bfloat162_rn(v.z, v.w);
        uint2 o;
        o.x = *reinterpret_cast<uint32_t*>(&lo);
        o.y = *reinterpret_cast<uint32_t*>(&hi);
        reinterpret_cast<uint2*>(g_Vb)[i] = o;
        return;
    }

    int bid = blockIdx.x - 256;                   // 0..63
    int e = bid >> 3;                             // 0..7
    int d0 = (bid & 7) * 64;                      // 0..511 step 64

    for (int i = t; i < 4096; i += 256) Cs[i >> 6][i & 63] = C[e * 4096 + i];
    for (int i = t; i < 4096; i += 256) Us[i >> 6][i & 63] = U[e * 32768 + d0 * 64 + i];
    __syncthreads();

    for (int o = t; o < 4096; o += 256) {
        int r = o >> 6, dl = o & 63;
        float s = 0.f;
#pragma unroll
        for (int ss = 0; ss < 64; ss++) s += Us[dl][ss] * Cs[r][ss];
        g_Utb[(size_t)(d0 + dl) * 512 + e * 64 + r] = __float2bfloat16(s);
    }
}

// ---------------- gate + x->bf16 fused: g = softmax(x@Wg^T + bg); g_Xb = bf16(x) ----------------
__global__ void gate_cvt_kernel(const float* __restrict__ x, const float* __restrict__ Wg,
                                const float* __restrict__ bg) {
    int warp = blockIdx.x * (blockDim.x >> 5) + (threadIdx.x >> 5);
    int lane = threadIdx.x & 31;
    if (warp >= BB) return;
    int m = warp;

    const float4* xr = reinterpret_cast<const float4*>(x + (size_t)m * 512);
    uint2* xb = reinterpret_cast<uint2*>(g_Xb + (size_t)m * 512);

    // hoist all x loads (MLP=4 on the DRAM-latency path)
    float4 xv[4];
#pragma unroll
    for (int i = 0; i < 4; i++) xv[i] = xr[lane + i * 32];
#pragma unroll
    for (int i = 0; i < 4; i++) {
        __nv_bfloat162 lo = __floats2bfloat162_rn(xv[i].x, xv[i].y);
        __nv_bfloat162 hi = __floats2bfloat162_rn(xv[i].z, xv[i].w);
        uint2 o;
        o.x = *reinterpret_cast<uint32_t*>(&lo);
        o.y = *reinterpret_cast<uint32_t*>(&hi);
        xb[lane + i * 32] = o;
    }

    float acc[8] = {0.f, 0.f, 0.f, 0.f, 0.f, 0.f, 0.f, 0.f};
#pragma unroll
    for (int i = 0; i < 4; i++) {
#pragma unroll
        for (int e = 0; e < 8; e++) {
            float4 wv = reinterpret_cast<const float4*>(Wg + e * 512)[lane + i * 32];
            acc[e] += xv[i].x * wv.x + xv[i].y * wv.y + xv[i].z * wv.z + xv[i].w * wv.w;
        }
    }
#pragma unroll
    for (int off = 16; off; off >>= 1)
#pragma unroll
        for (int e = 0; e < 8; e++) acc[e] += __shfl_xor_sync(0xFFFFFFFFu, acc[e], off);

    if (lane == 0) {
        float logit[8], mx = -1e30f;
#pragma unroll
        for (int e = 0; e < 8; e++) { logit[e] = acc[e] + bg[e]; mx = fmaxf(mx, logit[e]); }
        float ex[8], s = 0.f;
#pragma unroll
        for (int e = 0; e < 8; e++) { ex[e] = expf(logit[e] - mx); s += ex[e]; }
        float inv = 1.f / s;
#pragma unroll
        for (int e = 0; e < 8; e++) g_gate[m * 8 + e] = ex[e] * inv;
    }
}

// ---------------- bf16 mma.sync GEMM (R10 proven loop shape) ----------------
// D[128,128] tile; 128 thr, 4 warps in 2(m) x 2(n), warp tile 64x64.
// K chunks of 64, 2-stage cp.async double buffer, 2 CTAs/SM.
// mode 1: A=g_Xb, B=g_Vb; epilogue h = g*xv -> g_Hb (bf16)
// mode 2: A=g_Hb, B=g_Utb; epilogue out = x0*gproj + g@b + x*sum(g)
__global__ __launch_bounds__(128, 2) void gemm_mma(const __nv_bfloat16* __restrict__ A,
                                                   const __nv_bfloat16* __restrict__ Bp,
                                                   int mode,
                                                   const float* __restrict__ x0,
                                                   const float* __restrict__ x,
                                                   const float* __restrict__ bbias,
                                                   float* __restrict__ out) {
    extern __shared__ __align__(16) float smemf[];
    const uint32_t sb = smem_u32(smemf);
    const int tid = threadIdx.x;
    const int wid = tid >> 5, lane = tid & 31;
    const int g = lane >> 2, tg = lane & 3;       // accum frag coords
    const int wm = wid & 1, wn = wid >> 1;        // warp m (0..1), n (0..1)
    const int n0 = blockIdx.x * 128, m0 = blockIdx.y * 128;

    float acc[4][8][4];
#pragma unroll
    for (int mi = 0; mi < 4; mi++)
#pragma unroll
        for (int ni = 0; ni < 8; ni++)
#pragma unroll
            for (int q = 0; q < 4; q++) acc[mi][ni][q] = 0.f;

    // ldmatrix lane->address maps (add stage*OPS_B + ks*32 at use)
    const int arow_l = (lane & 7) + ((lane >> 3) & 1) * 8;
    const int ahalf  = ((lane >> 4) & 1) * 16;
    uint32_t a_addr[4];
#pragma unroll
    for (int mi = 0; mi < 4; mi++)
        a_addr[mi] = sb + (uint32_t)(wm * 64 + mi * 16 + arow_l) * ROWB + ahalf;
    const int brow_l = (lane & 7) + ((lane >> 4) & 1) * 8;
    const int bhalf  = ((lane >> 3) & 1) * 16;
    uint32_t b_addr[4];
#pragma unroll
    for (int bj = 0; bj < 4; bj++)
        b_addr[bj] = sb + STAGE_B + (uint32_t)(wn * 64 + bj * 16 + brow_l) * ROWB + bhalf;

    // chunk load: 128 rows x 128B per operand; 16 cp16 per thread
#define LOADCHUNK(SLOT, KC) do {                                                         \
        const __nv_bfloat16* _ag = A  + (size_t)m0 * 512 + (KC) * 64;                    \
        const __nv_bfloat16* _bg = Bp + (size_t)n0 * 512 + (KC) * 64;                    \
        uint32_t _ab = sb + (SLOT) * OPS_B;                                              \
        uint32_t _bb = _ab + STAGE_B;                                                    \
        _Pragma("unroll")                                                                \
        for (int j = 0; j < 8; j++) {                                                    \
            int id = tid + j * 128;                                                      \
            int row = id >> 3, seg = id & 7;                                             \
            cp16s(_ab + row * ROWB + seg * 16, _ag + (size_t)row * 512 + seg * 8);       \
            cp16s(_bb + row * ROWB + seg * 16, _bg + (size_t)row * 512 + seg * 8);       \
        }                                                                                \
        asm volatile("cp.async.commit_group;");                                          \
    } while (0)

    LOADCHUNK(0, 0);

    for (int c = 0; c < 8; c++) {
        if (c < 7) LOADCHUNK((c + 1) & 1, c + 1);
        if (c < 7) asm volatile("cp.async.wait_group 1;");
        else       asm volatile("cp.async.wait_group 0;");
        __syncthreads();

        const uint32_t soff = (uint32_t)(c & 1) * OPS_B;
#pragma unroll
        for (int ks = 0; ks < 4; ks++) {
            const uint32_t ko = soff + ks * 32;
            uint32_t a[4][4];
#pragma unroll
            for (int mi = 0; mi < 4; mi++) ldsm4(a[mi], a_addr[mi] + ko);
            uint32_t b[4][4];
#pragma unroll
            for (int bj = 0; bj < 4; bj++) ldsm4(b[bj], b_addr[bj] + ko);
#pragma unroll
            for (int ni = 0; ni < 8; ni++) {
                uint32_t b0 = b[ni >> 1][(ni & 1) * 2];
                uint32_t b1 = b[ni >> 1][(ni & 1) * 2 + 1];
#pragma unroll
                for (int mi = 0; mi < 4; mi++) mma_bf16(acc[mi][ni], a[mi], b0, b1);
            }
        }
        if (c < 7) __syncthreads();   // protect current buf before next-iter overwrite
    }
#undef LOADCHUNK

    // ---------------- epilogue ----------------
    // acc[mi][ni]: rows r0 = m0+wm*64+mi*16+g (c0,c1), r1 = r0+8 (c2,c3);
    // cols = n0 + wn*64 + ni*8 + 2*tg (+1)
    if (mode == 1) {
        const int e_w = (n0 + wn * 64) >> 6;   // expert constant per warp column strip
#pragma unroll
        for (int mi = 0; mi < 4; mi++) {
            int r0 = m0 + wm * 64 + mi * 16 + g, r1 = r0 + 8;
            float g0 = g_gate[r0 * 8 + e_w];
            float g1 = g_gate[r1 * 8 + e_w];
#pragma unroll
            for (int ni = 0; ni < 8; ni++) {
                int cc = n0 + wn * 64 + ni * 8 + 2 * tg;
                __nv_bfloat162 h0 = __floats2bfloat162_rn(g0 * acc[mi][ni][0], g0 * acc[mi][ni][1]);
                __nv_bfloat162 h1 = __floats2bfloat162_rn(g1 * acc[mi][ni][2], g1 * acc[mi][ni][3]);
                *reinterpret_cast<__nv_bfloat162*>(&g_Hb[(size_t)r0 * 512 + cc]) = h0;
                *reinterpret_cast<__nv_bfloat162*>(&g_Hb[(size_t)r1 * 512 + cc]) = h1;
            }
        }
    } else {
        // stage b columns for this CTA: bs[e][0..127]
        __syncthreads();
        float* bs = smemf;
        for (int i = tid; i < 8 * 128; i += 128)
            bs[i] = bbias[(i >> 7) * 512 + n0 + (i & 127)];
        __syncthreads();

#pragma unroll
        for (int ni = 0; ni < 8; ni++) {
            int cl = wn * 64 + ni * 8 + 2 * tg;
            int cc = n0 + cl;
            float bc0[8], bc1[8];
#pragma unroll
            for (int e = 0; e < 8; e++) { bc0[e] = bs[e * 128 + cl]; bc1[e] = bs[e * 128 + cl + 1]; }
#pragma unroll
            for (int mi = 0; mi < 4; mi++) {
                int r0 = m0 + wm * 64 + mi * 16 + g;
#pragma unroll
                for (int rr = 0; rr < 2; rr++) {
                    int r = r0 + rr * 8;
                    float4 ga = *reinterpret_cast<const float4*>(g_gate + r * 8);
                    float4 gb = *reinterpret_cast<const float4*>(g_gate + r * 8 + 4);
                    float gs = ga.x + ga.y + ga.z + ga.w + gb.x + gb.y + gb.z + gb.w;
                    float q0 = ga.x * bc0[0] + ga.y * bc0[1] + ga.z * bc0[2] + ga.w * bc0[3]
                             + gb.x * bc0[4] + gb.y * bc0[5] + gb.z * bc0[6] + gb.w * bc0[7];
                    float q1 = ga.x * bc1[0] + ga.y * bc1[1] + ga.z * bc1[2] + ga.w * bc1[3]
                             + gb.x * bc1[4] + gb.y * bc1[5] + gb.z * bc1[6] + gb.w * bc1[7];
                    size_t off = (size_t)r * 512 + cc;
                    float2 xv0 = *reinterpret_cast<const float2*>(x0 + off);
                    float2 xv  = *reinterpret_cast<const float2*>(x + off);
                    float a0 = acc[mi][ni][rr ? 2 : 0];
                    float a1 = acc[mi][ni][rr ? 3 : 1];
                    float2 o;
                    o.x = fmaf(xv0.x, a0, fmaf(xv.x, gs, q0));
                    o.y = fmaf(xv0.y, a1, fmaf(xv.y, gs, q1));
                    *reinterpret_cast<float2*>(out + off) = o;
                }
            }
        }
    }
}

// ---------------- launch ----------------
extern "C" void kernel_launch(void* const* d_in, const int* in_sizes, int n_in,
                              void* d_out, int out_size) {
    const float* x0 = (const float*)d_in[0];   // [B, D]
    const float* x  = (const float*)d_in[1];   // [B, D]
    const float* U  = (const float*)d_in[2];   // [E, D, R]
    const float* V  = (const float*)d_in[3];   // [E, R, D]
    const float* C  = (const float*)d_in[4];   // [E, R, R]
    const float* b  = (const float*)d_in[5];   // [E, D]
    const float* Wg = (const float*)d_in[6];   // [E, D]
    const float* bg = (const float*)d_in[7];   // [E]
    float* out = (float*)d_out;

    cudaFuncSetAttribute(gemm_mma, cudaFuncAttributeMaxDynamicSharedMemorySize, SM_TOTAL);

    prep_kernel<<<320, 256>>>(V, U, C);          // V->bf16 + C-fold
    gate_cvt_kernel<<<2048, 256>>>(x, Wg, bg);   // gates + x->bf16 in one pass

    const __nv_bfloat16 *Xb, *Vb, *Hb, *Utb;
    cudaGetSymbolAddress((void**)&Xb, g_Xb);
    cudaGetSymbolAddress((void**)&Vb, g_Vb);
    cudaGetSymbolAddress((void**)&Hb, g_Hb);
    cudaGetSymbolAddress((void**)&Utb, g_Utb);

    // GEMM1: g_Hb = g * (x @ Vflat^T)
    gemm_mma<<<dim3(4, 128), 128, SM_TOTAL>>>(Xb, Vb, 1, nullptr, nullptr, nullptr, nullptr);
    // GEMM2: out = x0 * (g_Hb @ Ut^T) + g@b + x*sum(g)
    gemm_mma<<<dim3(4, 128), 128, SM_TOTAL>>>(Hb, Utb, 2, x0, x, b, out);
}

// round 13
// speedup vs baseline: 1.1730x; 1.0347x over previous
#include <cuda_runtime.h>
#include <cuda_bf16.h>
#include <cstdint>
#include <math.h>

// Problem sizes (fixed)
#define BB 16384
#define DD 512

// ---------------- scratch (device globals; no allocs allowed) ----------------
__device__ __nv_bfloat16 g_Vb[512 * 512];    // B1: V bf16, rows n=(e,r), k=d contiguous
__device__ __nv_bfloat16 g_Utb[512 * 512];   // B2: Ut[n=d][k=e*64+r] bf16 (C folded into U)
__device__ __nv_bfloat16 g_Xb[BB * 512];     // x bf16 (A operand GEMM1)
__device__ __nv_bfloat16 g_Hb[BB * 512];     // h = g*xv bf16 (A operand GEMM2)
__device__ float g_gate[BB * 8];             // softmax gates

// ---------------- helpers ----------------
__device__ __forceinline__ uint32_t smem_u32(const void* p) {
    uint32_t a;
    asm("{ .reg .u64 t; cvta.to.shared.u64 t, %1; cvt.u32.u64 %0, t; }" : "=r"(a) : "l"(p));
    return a;
}
__device__ __forceinline__ void cp16s(uint32_t s, const void* g) {
    asm volatile("cp.async.cg.shared.global [%0], [%1], 16;" :: "r"(s), "l"(g));
}
__device__ __forceinline__ void pfL2(const void* g) {
    asm volatile("prefetch.global.L2 [%0];" :: "l"(g));
}
__device__ __forceinline__ void ldsm4(uint32_t* r, uint32_t addr) {
    asm volatile("ldmatrix.sync.aligned.m8n8.x4.shared.b16 {%0,%1,%2,%3}, [%4];"
        : "=r"(r[0]), "=r"(r[1]), "=r"(r[2]), "=r"(r[3]) : "r"(addr));
}
// m16n8k16 bf16 MMA, fp32 accum
__device__ __forceinline__ void mma_bf16(float* d, const uint32_t* a, uint32_t b0, uint32_t b1) {
    asm volatile(
        "mma.sync.aligned.m16n8k16.row.col.f32.bf16.bf16.f32 "
        "{%0,%1,%2,%3}, {%4,%5,%6,%7}, {%8,%9}, {%0,%1,%2,%3};"
        : "+f"(d[0]), "+f"(d[1]), "+f"(d[2]), "+f"(d[3])
        : "r"(a[0]), "r"(a[1]), "r"(a[2]), "r"(a[3]), "r"(b0), "r"(b1));
}

// smem geometry: chunk = 128 rows x 64 bf16 (128B) per operand, padded to 144B/row.
static constexpr int ROWB = 144;                 // bytes per smem row
static constexpr int STAGE_B = 128 * ROWB;       // 18432 B per operand per stage
static constexpr int OPS_B = 2 * STAGE_B;        // 36864 B per stage (A + B)
static constexpr int SM_TOTAL = 2 * OPS_B;       // 73728 B (2 stages) — proven config

// ---------------- fused prep + gate:
// blocks 0..2047: gate softmax + x->bf16;  2048..2303: V->bf16;  2304..2367: fold C into U
__global__ void prep_gate_kernel(const float* __restrict__ x, const float* __restrict__ Wg,
                                 const float* __restrict__ bg, const float* __restrict__ V,
                                 const float* __restrict__ U, const float* __restrict__ C) {
    __shared__ float Cs[64][64];
    __shared__ float Us[64][65];
    int t = threadIdx.x;

    if (blockIdx.x < 2048) {
        int warp = blockIdx.x * 8 + (t >> 5);
        int lane = t & 31;
        int m = warp;

        const float4* xr = reinterpret_cast<const float4*>(x + (size_t)m * 512);
        uint2* xb = reinterpret_cast<uint2*>(g_Xb + (size_t)m * 512);

        float4 xv[4];
#pragma unroll
        for (int i = 0; i < 4; i++) xv[i] = xr[lane + i * 32];
#pragma unroll
        for (int i = 0; i < 4; i++) {
            __nv_bfloat162 lo = __floats2bfloat162_rn(xv[i].x, xv[i].y);
            __nv_bfloat162 hi = __floats2bfloat162_rn(xv[i].z, xv[i].w);
            uint2 o;
            o.x = *reinterpret_cast<uint32_t*>(&lo);
            o.y = *reinterpret_cast<uint32_t*>(&hi);
            xb[lane + i * 32] = o;
        }

        float acc[8] = {0.f, 0.f, 0.f, 0.f, 0.f, 0.f, 0.f, 0.f};
#pragma unroll
        for (int i = 0; i < 4; i++) {
#pragma unroll
            for (int e = 0; e < 8; e++) {
                float4 wv = reinterpret_cast<const float4*>(Wg + e * 512)[lane + i * 32];
                acc[e] += xv[i].x * wv.x + xv[i].y * wv.y + xv[i].z * wv.z + xv[i].w * wv.w;
            }
        }
#pragma unroll
        for (int off = 16; off; off >>= 1)
#pragma unroll
            for (int e = 0; e < 8; e++) acc[e] += __shfl_xor_sync(0xFFFFFFFFu, acc[e], off);

        if (lane == 0) {
            float logit[8], mx = -1e30f;
#pragma unroll
            for (int e = 0; e < 8; e++) { logit[e] = acc[e] + bg[e]; mx = fmaxf(mx, logit[e]); }
            float ex[8], s = 0.f;
#pragma unroll
            for (int e = 0; e < 8; e++) { ex[e] = expf(logit[e] - mx); s += ex[e]; }
            float inv = 1.f / s;
#pragma unroll
            for (int e = 0; e < 8; e++) g_gate[m * 8 + e] = ex[e] * inv;
        }
        return;
    }

    if (blockIdx.x < 2304) {
        // V fp32 -> bf16, 4 floats per thread
        int i = (blockIdx.x - 2048) * 256 + t;    // 0..65535 (x4 floats)
        float4 v = reinterpret_cast<const float4*>(V)[i];
        __nv_bfloat162 lo = __floats2bfloat162_rn(v.x, v.y);
        __nv_bfloat162 hi = __floats2bfloat162_rn(v.z, v.w);
        uint2 o;
        o.x = *reinterpret_cast<uint32_t*>(&lo);
        o.y = *reinterpret_cast<uint32_t*>(&hi);
        reinterpret_cast<uint2*>(g_Vb)[i] = o;
        return;
    }

    int bid = blockIdx.x - 2304;                  // 0..63
    int e = bid >> 3;                             // 0..7
    int d0 = (bid & 7) * 64;                      // 0..511 step 64

    for (int i = t; i < 4096; i += 256) Cs[i >> 6][i & 63] = C[e * 4096 + i];
    for (int i = t; i < 4096; i += 256) Us[i >> 6][i & 63] = U[e * 32768 + d0 * 64 + i];
    __syncthreads();

    for (int o = t; o < 4096; o += 256) {
        int r = o >> 6, dl = o & 63;
        float s = 0.f;
#pragma unroll
        for (int ss = 0; ss < 64; ss++) s += Us[dl][ss] * Cs[r][ss];
        g_Utb[(size_t)(d0 + dl) * 512 + e * 64 + r] = __float2bfloat16(s);
    }
}

// ---------------- bf16 mma.sync GEMM (R10 proven loop shape) ----------------
// D[128,128] tile; 128 thr, 4 warps in 2(m) x 2(n), warp tile 64x64.
// K chunks of 64, 2-stage cp.async double buffer, 2 CTAs/SM.
// mode 1: A=g_Xb, B=g_Vb; epilogue h = g*xv -> g_Hb (bf16)
// mode 2: A=g_Hb, B=g_Utb; epilogue out = x0*gproj + g@b + x  (sum(g)==1)
__global__ __launch_bounds__(128, 2) void gemm_mma(const __nv_bfloat16* __restrict__ A,
                                                   const __nv_bfloat16* __restrict__ Bp,
                                                   int mode,
                                                   const float* __restrict__ x0,
                                                   const float* __restrict__ x,
                                                   const float* __restrict__ bbias,
                                                   float* __restrict__ out) {
    extern __shared__ __align__(16) float smemf[];
    const uint32_t sb = smem_u32(smemf);
    const int tid = threadIdx.x;
    const int wid = tid >> 5, lane = tid & 31;
    const int g = lane >> 2, tg = lane & 3;       // accum frag coords
    const int wm = wid & 1, wn = wid >> 1;        // warp m (0..1), n (0..1)
    const int n0 = blockIdx.x * 128, m0 = blockIdx.y * 128;

    // L2-prefetch the epilogue working set; DRAM fetch overlaps the mainloop.
    if (mode == 2) {
#pragma unroll
        for (int j = 0; j < 4; j++) {
            int i = tid + j * 128;                 // 0..511: (row, 128B-seg)
            int row = i >> 2, seg = i & 3;
            size_t off = (size_t)(m0 + row) * 512 + n0 + seg * 32;
            pfL2(x0 + off);
            pfL2(x + off);
        }
        if (tid < 32) pfL2(g_gate + (size_t)m0 * 8 + tid * 32);
    }

    float acc[4][8][4];
#pragma unroll
    for (int mi = 0; mi < 4; mi++)
#pragma unroll
        for (int ni = 0; ni < 8; ni++)
#pragma unroll
            for (int q = 0; q < 4; q++) acc[mi][ni][q] = 0.f;

    // ldmatrix lane->address maps (add stage*OPS_B + ks*32 at use)
    const int arow_l = (lane & 7) + ((lane >> 3) & 1) * 8;
    const int ahalf  = ((lane >> 4) & 1) * 16;
    uint32_t a_addr[4];
#pragma unroll
    for (int mi = 0; mi < 4; mi++)
        a_addr[mi] = sb + (uint32_t)(wm * 64 + mi * 16 + arow_l) * ROWB + ahalf;
    const int brow_l = (lane & 7) + ((lane >> 4) & 1) * 8;
    const int bhalf  = ((lane >> 3) & 1) * 16;
    uint32_t b_addr[4];
#pragma unroll
    for (int bj = 0; bj < 4; bj++)
        b_addr[bj] = sb + STAGE_B + (uint32_t)(wn * 64 + bj * 16 + brow_l) * ROWB + bhalf;

    // chunk load: 128 rows x 128B per operand; 16 cp16 per thread
#define LOADCHUNK(SLOT, KC) do {                                                         \
        const __nv_bfloat16* _ag = A  + (size_t)m0 * 512 + (KC) * 64;                    \
        const __nv_bfloat16* _bg = Bp + (size_t)n0 * 512 + (KC) * 64;                    \
        uint32_t _ab = sb + (SLOT) * OPS_B;                                              \
        uint32_t _bb = _ab + STAGE_B;                                                    \
        _Pragma("unroll")                                                                \
        for (int j = 0; j < 8; j++) {                                                    \
            int id = tid + j * 128;                                                      \
            int row = id >> 3, seg = id & 7;                                             \
            cp16s(_ab + row * ROWB + seg * 16, _ag + (size_t)row * 512 + seg * 8);       \
            cp16s(_bb + row * ROWB + seg * 16, _bg + (size_t)row * 512 + seg * 8);       \
        }                                                                                \
        asm volatile("cp.async.commit_group;");                                          \
    } while (0)

    LOADCHUNK(0, 0);

    for (int c = 0; c < 8; c++) {
        if (c < 7) LOADCHUNK((c + 1) & 1, c + 1);
        if (c < 7) asm volatile("cp.async.wait_group 1;");
        else       asm volatile("cp.async.wait_group 0;");
        __syncthreads();

        const uint32_t soff = (uint32_t)(c & 1) * OPS_B;
#pragma unroll
        for (int ks = 0; ks < 4; ks++) {
            const uint32_t ko = soff + ks * 32;
            uint32_t a[4][4];
#pragma unroll
            for (int mi = 0; mi < 4; mi++) ldsm4(a[mi], a_addr[mi] + ko);
            uint32_t b[4][4];
#pragma unroll
            for (int bj = 0; bj < 4; bj++) ldsm4(b[bj], b_addr[bj] + ko);
#pragma unroll
            for (int ni = 0; ni < 8; ni++) {
                uint32_t b0 = b[ni >> 1][(ni & 1) * 2];
                uint32_t b1 = b[ni >> 1][(ni & 1) * 2 + 1];
#pragma unroll
                for (int mi = 0; mi < 4; mi++) mma_bf16(acc[mi][ni], a[mi], b0, b1);
            }
        }
        if (c < 7) __syncthreads();   // protect current buf before next-iter overwrite
    }
#undef LOADCHUNK

    // ---------------- epilogue ----------------
    // acc[mi][ni]: rows r0 = m0+wm*64+mi*16+g (c0,c1), r1 = r0+8 (c2,c3);
    // cols = n0 + wn*64 + ni*8 + 2*tg (+1)
    if (mode == 1) {
        const int e_w = (n0 + wn * 64) >> 6;   // expert constant per warp column strip
#pragma unroll
        for (int mi = 0; mi < 4; mi++) {
            int r0 = m0 + wm * 64 + mi * 16 + g, r1 = r0 + 8;
            float g0 = g_gate[r0 * 8 + e_w];
            float g1 = g_gate[r1 * 8 + e_w];
#pragma unroll
            for (int ni = 0; ni < 8; ni++) {
                int cc = n0 + wn * 64 + ni * 8 + 2 * tg;
                __nv_bfloat162 h0 = __floats2bfloat162_rn(g0 * acc[mi][ni][0], g0 * acc[mi][ni][1]);
                __nv_bfloat162 h1 = __floats2bfloat162_rn(g1 * acc[mi][ni][2], g1 * acc[mi][ni][3]);
                *reinterpret_cast<__nv_bfloat162*>(&g_Hb[(size_t)r0 * 512 + cc]) = h0;
                *reinterpret_cast<__nv_bfloat162*>(&g_Hb[(size_t)r1 * 512 + cc]) = h1;
            }
        }
    } else {
        // stage b columns for this CTA: bs[e][0..127]
        __syncthreads();
        float* bs = smemf;
        for (int i = tid; i < 8 * 128; i += 128)
            bs[i] = bbias[(i >> 7) * 512 + n0 + (i & 127)];
        __syncthreads();

        const int clb = wn * 64 + 2 * tg;          // column base within tile
#pragma unroll
        for (int mi = 0; mi < 4; mi++) {
            int r0 = m0 + wm * 64 + mi * 16 + g;
#pragma unroll
            for (int rr = 0; rr < 2; rr++) {
                int r = r0 + rr * 8;
                // batch-issue all 16 epilogue loads for this row (MLP=16)
                float2 xv0[8], xv[8];
#pragma unroll
                for (int ni = 0; ni < 8; ni++) {
                    size_t off = (size_t)r * 512 + n0 + clb + ni * 8;
                    xv0[ni] = *reinterpret_cast<const float2*>(x0 + off);
                    xv[ni]  = *reinterpret_cast<const float2*>(x + off);
                }
                float4 ga = *reinterpret_cast<const float4*>(g_gate + r * 8);
                float4 gb = *reinterpret_cast<const float4*>(g_gate + r * 8 + 4);
#pragma unroll
                for (int ni = 0; ni < 8; ni++) {
                    int cl = clb + ni * 8;
                    float q0 = ga.x * bs[cl] + ga.y * bs[128 + cl] + ga.z * bs[256 + cl]
                             + ga.w * bs[384 + cl] + gb.x * bs[512 + cl] + gb.y * bs[640 + cl]
                             + gb.z * bs[768 + cl] + gb.w * bs[896 + cl];
                    float q1 = ga.x * bs[cl + 1] + ga.y * bs[129 + cl] + ga.z * bs[257 + cl]
                             + ga.w * bs[385 + cl] + gb.x * bs[513 + cl] + gb.y * bs[641 + cl]
                             + gb.z * bs[769 + cl] + gb.w * bs[897 + cl];
                    float a0 = acc[mi][ni][rr ? 2 : 0];
                    float a1 = acc[mi][ni][rr ? 3 : 1];
                    float2 o;
                    o.x = fmaf(xv0[ni].x, a0, xv[ni].x + q0);   // sum(g) == 1
                    o.y = fmaf(xv0[ni].y, a1, xv[ni].y + q1);
                    *reinterpret_cast<float2*>(out + (size_t)r * 512 + n0 + cl) = o;
                }
            }
        }
    }
}

// ---------------- launch ----------------
extern "C" void kernel_launch(void* const* d_in, const int* in_sizes, int n_in,
                              void* d_out, int out_size) {
    const float* x0 = (const float*)d_in[0];   // [B, D]
    const float* x  = (const float*)d_in[1];   // [B, D]
    const float* U  = (const float*)d_in[2];   // [E, D, R]
    const float* V  = (const float*)d_in[3];   // [E, R, D]
    const float* C  = (const float*)d_in[4];   // [E, R, R]
    const float* b  = (const float*)d_in[5];   // [E, D]
    const float* Wg = (const float*)d_in[6];   // [E, D]
    const float* bg = (const float*)d_in[7];   // [E]
    float* out = (float*)d_out;

    cudaFuncSetAttribute(gemm_mma, cudaFuncAttributeMaxDynamicSharedMemorySize, SM_TOTAL);

    prep_gate_kernel<<<2368, 256>>>(x, Wg, bg, V, U, C);   // gate + x->bf16 + V->bf16 + C-fold

    const __nv_bfloat16 *Xb, *Vb, *Hb, *Utb;
    cudaGetSymbolAddress((void**)&Xb, g_Xb);
    cudaGetSymbolAddress((void**)&Vb, g_Vb);
    cudaGetSymbolAddress((void**)&Hb, g_Hb);
    cudaGetSymbolAddress((void**)&Utb, g_Utb);

    // GEMM1: g_Hb = g * (x @ Vflat^T)
    gemm_mma<<<dim3(4, 128), 128, SM_TOTAL>>>(Xb, Vb, 1, nullptr, nullptr, nullptr, nullptr);
    // GEMM2: out = x0 * (g_Hb @ Ut^T) + g@b + x
    gemm_mma<<<dim3(4, 128), 128, SM_TOTAL>>>(Hb, Utb, 2, x0, x, b, out);
}